// round 13
// baseline (speedup 1.0000x reference)
#include <cuda_runtime.h>
#include <stdint.h>

// Problem: emb_in [2048, 32] f32, sum_weights [2048] f32.
// Output [2048*2048, 65] f32, row k = i*2048 + j:
//   out[k][0:32]=emb[i], out[k][32:64]=emb[j], out[k][64]=w[j].
//
// R9/R11 (best, 145.5us, DRAM 89.7%): block-wide smem fill, ONE bulk
// TMA store per 128-row chunk, issued after __syncthreads by tid 0.
// R13 (retry of R12 after infra failure): decouple warps. Each warp
// owns a contiguous 16-row (4160 B) slice: fill -> __syncwarp ->
// fence -> its own cp.async.bulk -> wait_group.read 0. No block syncs;
// the first sub-store hits the TMA queue as soon as ONE warp is done
// instead of after the slowest of 8. 8 independent TMA streams per CTA
// smooth DRAM queue occupancy.

#define N_ROWS     2048
#define ROW_LEN    65
#define R_CHUNK    128                           // rows per CTA
#define W_ROWS     16                            // rows per warp
#define W_F        (W_ROWS * ROW_LEN)            // 1040 floats per warp slice
#define W_B        (W_F * 4)                     // 4160 bytes (mult of 16)
#define CHUNK_F    (R_CHUNK * ROW_LEN)           // 8320 floats
#define N_CHUNKS   (N_ROWS * N_ROWS / R_CHUNK)   // 32768 blocks

__global__ __launch_bounds__(256)
void no_sparsity_warp_tma_kernel(const float* __restrict__ emb,
                                 const float* __restrict__ w,
                                 float* __restrict__ out)
{
    __shared__ __align__(16) float s[CHUNK_F];   // 33,280 B

    const unsigned k0 = blockIdx.x * (unsigned)R_CHUNK;  // first output row
    const unsigned i  = k0 >> 11;                        // constant per block
    const unsigned j0 = k0 & 2047u;

    const int tid  = threadIdx.x;
    const int lane = tid & 31;
    const int wr   = tid >> 5;                           // warp id, 0..7

    // emb[i][lane]: one broadcast 128B line, L1-resident across the block.
    const float a = __ldg(emb + i * 32u + lane);

    // ---- Warp wr fills its contiguous rows [wr*16, wr*16+16) ----
    // Row stride 65 == 1 (mod 32) -> bank = (r + lane) % 32, conflict-free.
    const int r0 = wr * W_ROWS;
    float* wbuf = s + r0 * ROW_LEN;
#pragma unroll
    for (int rr = 0; rr < W_ROWS; ++rr) {
        const unsigned j = j0 + (unsigned)(r0 + rr);
        const float b = __ldg(emb + j * 32u + lane);     // coalesced 128B row
        float* srow = wbuf + rr * ROW_LEN;
        srow[lane]      = a;                             // cols 0..31
        srow[32 + lane] = b;                             // cols 32..63
        if (lane == 0) srow[64] = __ldg(w + j);          // col 64
    }
    __syncwarp();   // all 32 lanes' STS done before the elected issue

    // ---- Warp-private drain: one bulk TMA store of this slice ----
    if (lane == 0) {
        // Order this warp's generic-proxy STS before the async-proxy read.
        asm volatile("fence.proxy.async.shared::cta;" ::: "memory");
        const float* dst = out + (size_t)blockIdx.x * (size_t)CHUNK_F
                               + (size_t)(r0 * ROW_LEN);
        uint32_t saddr = (uint32_t)__cvta_generic_to_shared(wbuf);
        asm volatile(
            "cp.async.bulk.global.shared::cta.bulk_group [%0], [%1], %2;"
            :: "l"(dst), "r"(saddr), "r"((unsigned)W_B)
            : "memory");
        asm volatile("cp.async.bulk.commit_group;" ::: "memory");
        // Smem reads must finish before this CTA's smem is retired; the
        // gmem write side drains while the next CTA ramps.
        asm volatile("cp.async.bulk.wait_group.read 0;" ::: "memory");
    }
}

extern "C" void kernel_launch(void* const* d_in, const int* in_sizes, int n_in,
                              void* d_out, int out_size)
{
    const float* emb = (const float*)d_in[0];   // [2048, 32] f32
    const float* w   = (const float*)d_in[1];   // [2048]     f32
    float* out       = (float*)d_out;

    no_sparsity_warp_tma_kernel<<<N_CHUNKS, 256>>>(emb, w, out);
}

// round 14
// speedup vs baseline: 1.0009x; 1.0009x over previous
#include <cuda_runtime.h>
#include <stdint.h>

// Problem: emb_in [2048, 32] f32, sum_weights [2048] f32.
// Output [2048*2048, 65] f32, row k = i*2048 + j:
//   out[k][0:32]=emb[i], out[k][32:64]=emb[j], out[k][64]=w[j].
//
// FINAL (R11 lock-in). Evidence of convergence:
//   R9  (block TMA, full exit wait)      145.5us  DRAM 89.6%  7101 GB/s
//   R11 (block TMA, read-only exit wait) 145.5us  DRAM 89.7%  7110 GB/s
//   R13 (8 per-warp TMA streams)         145.6us  DRAM 89.5%  7095 GB/s
// Occupancy 36->63%, sub-store size 8x, sync structure all varied;
// throughput pinned at ~7.1 TB/s = the path-independent LTS chip cap
// (~6300 B/cyc, B300_MICROARCH). Traffic is compulsory-minimal:
// full-sector 128B-aligned writes (no RMW), inputs L2-resident.
//
// Design: each CTA stages 128 output rows (33,280 B) in smem with a
// structured fill (broadcast emb[i] from registers, one coalesced
// 128B LDG per emb[j] row, scalar w[j]), then drains the contiguous,
// 16B-aligned chunk with ONE cp.async.bulk (TMA) store — no LDS, no
// STG, no L1tex copy-out traffic. Exit waits only on the TMA's smem
// READS; the DRAM write side drains while the next CTA ramps.

#define N_ROWS     2048
#define ROW_LEN    65
#define R_CHUNK    128
#define CHUNK_F    (R_CHUNK * ROW_LEN)          // 8320 floats
#define CHUNK_B    (CHUNK_F * 4)                // 33,280 bytes (mult of 16)
#define N_CHUNKS   (N_ROWS * N_ROWS / R_CHUNK)  // 32768 blocks

__global__ __launch_bounds__(256)
void no_sparsity_tma_kernel(const float* __restrict__ emb,
                            const float* __restrict__ w,
                            float* __restrict__ out)
{
    __shared__ __align__(16) float s[CHUNK_F];

    const unsigned k0 = blockIdx.x * (unsigned)R_CHUNK;  // first output row
    const unsigned i  = k0 >> 11;                        // constant per block
    const unsigned j0 = k0 & 2047u;

    const int tid  = threadIdx.x;
    const int lane = tid & 31;
    const int wr   = tid >> 5;                           // warp id, 0..7

    // emb[i][lane]: one broadcast 128B line, L1-resident across the block.
    const float a = __ldg(emb + i * 32u + lane);

    // ---- Fill smem image. Warp wr handles rows wr, wr+8, ... (16 rows) ----
    // Row stride 65 == 1 (mod 32) -> bank = (r + lane) % 32, conflict-free.
#pragma unroll
    for (int r = wr; r < R_CHUNK; r += 8) {
        const unsigned j = j0 + (unsigned)r;
        const float b = __ldg(emb + j * 32u + lane);     // coalesced 128B row
        float* srow = s + r * ROW_LEN;
        srow[lane]      = a;                             // cols 0..31
        srow[32 + lane] = b;                             // cols 32..63
        if (lane == 0) srow[64] = __ldg(w + j);          // col 64
    }
    __syncthreads();

    // Order generic-proxy STS writes before the async-proxy TMA read.
    asm volatile("fence.proxy.async.shared::cta;" ::: "memory");

    // ---- Drain: one bulk TMA store, smem -> gmem ----
    if (tid == 0) {
        const float* dst = out + (size_t)blockIdx.x * (size_t)CHUNK_F;
        uint32_t saddr = (uint32_t)__cvta_generic_to_shared(s);
        asm volatile(
            "cp.async.bulk.global.shared::cta.bulk_group [%0], [%1], %2;"
            :: "l"(dst), "r"(saddr), "r"((unsigned)CHUNK_B)
            : "memory");
        asm volatile("cp.async.bulk.commit_group;" ::: "memory");
        // Wait only for the smem READS: that is all that must complete
        // before this CTA's smem can be retired. The gmem write side
        // drains while the next CTA ramps on this SM.
        asm volatile("cp.async.bulk.wait_group.read 0;" ::: "memory");
    }
}

extern "C" void kernel_launch(void* const* d_in, const int* in_sizes, int n_in,
                              void* d_out, int out_size)
{
    const float* emb = (const float*)d_in[0];   // [2048, 32] f32
    const float* w   = (const float*)d_in[1];   // [2048]     f32
    float* out       = (float*)d_out;

    no_sparsity_tma_kernel<<<N_CHUNKS, 256>>>(emb, w, out);
}

// round 16
// speedup vs baseline: 1.0018x; 1.0009x over previous
#include <cuda_runtime.h>
#include <stdint.h>

// Problem: emb_in [2048, 32] f32, sum_weights [2048] f32.
// Output [2048*2048, 65] f32, row k = i*2048 + j:
//   out[k][0:32]=emb[i], out[k][32:64]=emb[j], out[k][64]=w[j].
//
// Converged evidence (all ~7.1 TB/s, DRAM ~89.7%):
//   R9  block TMA 33KB, full exit wait        145.5us
//   R11 block TMA 33KB, read-only exit wait   145.5us
//   R13 8x per-warp 4KB TMA streams           145.6us
//   R14 R11 confirmation                      145.5us
// R15 probes the last untested axis on the TMA path: R_CHUNK=64
// (16,640 B smem -> ~13 resident CTAs/SM instead of 6). More
// independent fill/drain pipelines per SM + smoother wave tails.
// Cap theory predicts NEUTRAL (145.5 +/- 1.5us); <=143us would
// falsify it and reopen chunk-size tuning.
//
// Alignment: k0 = 64*blockIdx, 64*65 = 4160 floats (mult of 4) ->
// every chunk base is 16B-aligned; 64 | 2048 -> no i crossing.

#define N_ROWS     2048
#define ROW_LEN    65
#define R_CHUNK    64
#define CHUNK_F    (R_CHUNK * ROW_LEN)          // 4160 floats
#define CHUNK_B    (CHUNK_F * 4)                // 16,640 bytes (mult of 16)
#define N_CHUNKS   (N_ROWS * N_ROWS / R_CHUNK)  // 65536 blocks

__global__ __launch_bounds__(256)
void no_sparsity_tma64_kernel(const float* __restrict__ emb,
                              const float* __restrict__ w,
                              float* __restrict__ out)
{
    __shared__ __align__(16) float s[CHUNK_F];

    const unsigned k0 = blockIdx.x * (unsigned)R_CHUNK;  // first output row
    const unsigned i  = k0 >> 11;                        // constant per block
    const unsigned j0 = k0 & 2047u;

    const int tid  = threadIdx.x;
    const int lane = tid & 31;
    const int wr   = tid >> 5;                           // warp id, 0..7

    // emb[i][lane]: one broadcast 128B line, L1-resident across the block.
    const float a = __ldg(emb + i * 32u + lane);

    // ---- Fill smem image. Warp wr handles rows wr, wr+8, ... (8 rows) ----
    // Row stride 65 == 1 (mod 32) -> bank = (r + lane) % 32, conflict-free.
#pragma unroll
    for (int r = wr; r < R_CHUNK; r += 8) {
        const unsigned j = j0 + (unsigned)r;
        const float b = __ldg(emb + j * 32u + lane);     // coalesced 128B row
        float* srow = s + r * ROW_LEN;
        srow[lane]      = a;                             // cols 0..31
        srow[32 + lane] = b;                             // cols 32..63
        if (lane == 0) srow[64] = __ldg(w + j);          // col 64
    }
    __syncthreads();

    // Order generic-proxy STS writes before the async-proxy TMA read.
    asm volatile("fence.proxy.async.shared::cta;" ::: "memory");

    // ---- Drain: one bulk TMA store, smem -> gmem ----
    if (tid == 0) {
        const float* dst = out + (size_t)blockIdx.x * (size_t)CHUNK_F;
        uint32_t saddr = (uint32_t)__cvta_generic_to_shared(s);
        asm volatile(
            "cp.async.bulk.global.shared::cta.bulk_group [%0], [%1], %2;"
            :: "l"(dst), "r"(saddr), "r"((unsigned)CHUNK_B)
            : "memory");
        asm volatile("cp.async.bulk.commit_group;" ::: "memory");
        // Wait only for the smem READS: that is all that must complete
        // before this CTA's smem can be retired. The gmem write side
        // drains while the next CTA ramps on this SM.
        asm volatile("cp.async.bulk.wait_group.read 0;" ::: "memory");
    }
}

extern "C" void kernel_launch(void* const* d_in, const int* in_sizes, int n_in,
                              void* d_out, int out_size)
{
    const float* emb = (const float*)d_in[0];   // [2048, 32] f32
    const float* w   = (const float*)d_in[1];   // [2048]     f32
    float* out       = (float*)d_out;

    no_sparsity_tma64_kernel<<<N_CHUNKS, 256>>>(emb, w, out);
}